// round 8
// baseline (speedup 1.0000x reference)
#include <cuda_runtime.h>
#include <cstdint>

#define E_TOT  (256*4096)
#define NNODE  (256*512)
#define DHID   64
#define BNUM   256
#define EPB    4096
#define NPB    512
#define KKEEP  1024
#define KDROP  3072

// chunk-major AB: [batch][chunk 0..127][node 0..511] float4
__device__ float g_AB[(size_t)BNUM * 128 * 512 * 4];
__device__ float g_scores[E_TOT];

__device__ __forceinline__ unsigned long long pk2(float x, float y) {
    unsigned long long r;
    asm("mov.b64 %0, {%1, %2};" : "=l"(r) : "f"(x), "f"(y));
    return r;
}
__device__ __forceinline__ void fma2(unsigned long long& d,
                                     unsigned long long a, unsigned long long b) {
    asm("fma.rn.f32x2 %0, %1, %2, %0;" : "+l"(d) : "l"(a), "l"(b));
}
__device__ __forceinline__ unsigned long long add2(unsigned long long a,
                                                   unsigned long long b) {
    unsigned long long r;
    asm("add.rn.f32x2 %0, %1, %2;" : "=l"(r) : "l"(a), "l"(b));
    return r;
}
__device__ __forceinline__ unsigned long long relu2(unsigned long long t) {
    float lo, hi;
    asm("mov.b64 {%0, %1}, %2;" : "=f"(lo), "=f"(hi) : "l"(t));
    lo = fmaxf(lo, 0.f); hi = fmaxf(hi, 0.f);
    unsigned long long r;
    asm("mov.b64 %0, {%1, %2};" : "=l"(r) : "f"(lo), "f"(hi));
    return r;
}

// ---------------------------------------------------------------------------
// K1: AB = h @ Wc. CTA = 64 rows x 256 cols (half of Wc). 512 threads,
// thread tile 8 rows x 4 cols -> 32 acc regs, <=64 total, 2 CTAs/SM (50% occ).
// Warp w: colgroup g = w>>3 (128 cols), rows (w&7)*8. Lane cols 4l (conflict-
// free LDS.128); h via 2 broadcast LDS.128.
// ---------------------------------------------------------------------------
__global__ void __launch_bounds__(512, 2) k1_gemm(const float* __restrict__ hmat,
                                                  const float* __restrict__ W1) {
    extern __shared__ float sm1[];
    float* Ws = sm1;              // [64][256]  64 KB
    float* hs = sm1 + 64 * 256;   // [64][68]   transposed h tile
    const int tid  = threadIdx.x;
    const int tile = blockIdx.x >> 1;
    const int half = blockIdx.x & 1;          // 0 = A-half of W1, 1 = B-half
    const int rowbase = tile * 64;
    const int b     = rowbase >> 9;
    const int nboff = rowbase & 511;

    #pragma unroll
    for (int j = 0; j < 8; ++j) {
        int i = tid + j * 512;
        int k = i >> 6, o4 = i & 63;
        *(float4*)(Ws + k * 256 + o4 * 4) =
            *(const float4*)(W1 + (size_t)(half * 64 + k) * 256 + o4 * 4);
    }
    #pragma unroll
    for (int j = 0; j < 2; ++j) {
        int i = tid + j * 512;
        int n = i >> 4, k4 = i & 15;
        float4 v = *(const float4*)(hmat + (size_t)(rowbase + n) * 64 + k4 * 4);
        hs[(k4 * 4 + 0) * 68 + n] = v.x;
        hs[(k4 * 4 + 1) * 68 + n] = v.y;
        hs[(k4 * 4 + 2) * 68 + n] = v.z;
        hs[(k4 * 4 + 3) * 68 + n] = v.w;
    }
    __syncthreads();

    const int w = tid >> 5, l = tid & 31;
    const int g  = w >> 3;          // col half-group (0: cols 0..127, 1: 128..255)
    const int r0 = (w & 7) * 8;     // 8 rows

    unsigned long long acc[8][2];
    #pragma unroll
    for (int i = 0; i < 8; ++i) { acc[i][0] = 0ull; acc[i][1] = 0ull; }

    const float* hrow = hs + r0;
    const float* Wcol = Ws + g * 128 + 4 * l;
    #pragma unroll 4
    for (int k = 0; k < 64; ++k) {
        float4 h0 = *(const float4*)(hrow + k * 68);       // broadcast
        float4 h1 = *(const float4*)(hrow + k * 68 + 4);   // broadcast
        ulonglong2 w0 = *(const ulonglong2*)(Wcol + k * 256);  // conflict-free
        float hv[8] = {h0.x, h0.y, h0.z, h0.w, h1.x, h1.y, h1.z, h1.w};
        #pragma unroll
        for (int i = 0; i < 8; ++i) {
            unsigned long long a2 = pk2(hv[i], hv[i]);
            fma2(acc[i][0], a2, w0.x);
            fma2(acc[i][1], a2, w0.y);
        }
    }

    // restage chunk-major: lane covers chunk cc = g*32 + l (cols 4l of group g)
    __syncthreads();
    float4* st = (float4*)sm1;    // [64][65] float4 (aliased, 66.6 KB)
    const int cc = g * 32 + l;
    #pragma unroll
    for (int i = 0; i < 8; ++i) {
        float4 v;
        *(unsigned long long*)&v.x = acc[i][0];
        *(unsigned long long*)&v.z = acc[i][1];
        st[cc * 65 + r0 + i] = v;
    }
    __syncthreads();
    float4* dst = (float4*)g_AB;
    #pragma unroll
    for (int j = 0; j < 8; ++j) {
        int idx = tid + j * 512;              // 0..4095
        int c2 = idx >> 6, node = idx & 63;
        dst[((size_t)b * 128 + half * 64 + c2) * 512 + nboff + node] = st[c2 * 65 + node];
    }
}

// ---------------------------------------------------------------------------
// K2: edge scores, 2 CTAs/batch, chunk-4 streaming, prefetch depth 2,
// packed f32x2 consumer math.
// ---------------------------------------------------------------------------
__global__ void __launch_bounds__(512) k2_edges(const float* __restrict__ b1,
                                                const float* __restrict__ W2,
                                                const float* __restrict__ b2p,
                                                const int*   __restrict__ ei) {
    __shared__ float As[2][512 * 4];
    __shared__ float Bs[2][512 * 4];
    __shared__ float w2s[256];
    __shared__ float b1s[256];
    const int tid = threadIdx.x;
    const int b   = blockIdx.x >> 1;
    const int eh  = blockIdx.x & 1;
    const int ebase = b * EPB + eh * 2048;

    if (tid < 64)       *(float4*)(w2s + tid * 4)        = *(const float4*)(W2 + tid * 4);
    else if (tid < 128) *(float4*)(b1s + (tid - 64) * 4) = *(const float4*)(b1 + (tid - 64) * 4);

    int roff[4], coff[4];
    unsigned long long acc2[4];
    #pragma unroll
    for (int i = 0; i < 4; ++i) {
        int e = ebase + tid + i * 512;
        roff[i] = (ei[e]         - b * NPB) * 4;
        coff[i] = (ei[E_TOT + e] - b * NPB) * 4;
        acc2[i] = 0ull;
    }

    const float4* gA = (const float4*)g_AB + (size_t)b * 128 * 512;
    float4 ra0 = gA[tid],                     rb0 = gA[(size_t)64 * 512 + tid];
    float4 ra1 = gA[(size_t)1 * 512 + tid],   rb1 = gA[(size_t)65 * 512 + tid];
    __syncthreads();

    for (int c = 0; c < 64; ++c) {
        const int buf = c & 1;
        // bias add (packed) + stage
        {
            ulonglong2 av = *(ulonglong2*)&ra0;
            ulonglong2 bv = *(const ulonglong2*)(b1s + c * 4);
            ulonglong2 wa;
            wa.x = add2(av.x, bv.x);
            wa.y = add2(av.y, bv.y);
            *(ulonglong2*)(As[buf] + tid * 4) = wa;
            *(float4*)(Bs[buf] + tid * 4) = rb0;
        }
        __syncthreads();
        ra0 = ra1; rb0 = rb1;
        if (c + 2 < 64) {
            ra1 = gA[(size_t)(c + 2)  * 512 + tid];
            rb1 = gA[(size_t)(c + 66) * 512 + tid];
        }
        const float4 w2v = *(const float4*)(w2s + c * 4);
        const unsigned long long w01 = pk2(w2v.x, w2v.y);
        const unsigned long long w23 = pk2(w2v.z, w2v.w);
        const float* Ab = As[buf];
        const float* Bb = Bs[buf];
        #pragma unroll
        for (int i = 0; i < 4; ++i) {
            ulonglong2 av = *(const ulonglong2*)(Ab + roff[i]);
            ulonglong2 bv = *(const ulonglong2*)(Bb + coff[i]);
            unsigned long long t0 = relu2(add2(av.x, bv.x));
            unsigned long long t1 = relu2(add2(av.y, bv.y));
            fma2(acc2[i], t0, w01);
            fma2(acc2[i], t1, w23);
        }
    }
    const float b2v = b2p[0];
    #pragma unroll
    for (int i = 0; i < 4; ++i) {
        float lo, hi;
        asm("mov.b64 {%0, %1}, %2;" : "=f"(lo), "=f"(hi) : "l"(acc2[i]));
        g_scores[ebase + tid + i * 512] = lo + hi + b2v;
    }
}

// ---------------------------------------------------------------------------
// K3: bitonic argsort + outputs + SMEM mask + fused segment-sum.
// ---------------------------------------------------------------------------
__global__ void __launch_bounds__(1024) k3_sort(const int* __restrict__ ei,
                                                const float* __restrict__ hmat,
                                                float* __restrict__ out) {
    __shared__ unsigned long long sk[4096];
    __shared__ float smask[512];
    __shared__ float red[16][64];
    const int b = blockIdx.x, tid = threadIdx.x;

    if (tid < 512) smask[tid] = 0.f;

    unsigned long long key[4];
    float4 sc = *(const float4*)(g_scores + b * EPB + tid * 4);
    float sv[4] = {sc.x, sc.y, sc.z, sc.w};
    #pragma unroll
    for (int r = 0; r < 4; ++r) {
        unsigned int u = __float_as_uint(sv[r]);
        unsigned int enc = (u & 0x80000000u) ? ~u : (u | 0x80000000u);
        key[r] = ((unsigned long long)(~enc) << 32) | (unsigned int)(tid * 4 + r);
    }

    for (int k = 2; k <= 4096; k <<= 1) {
        int j = k >> 1;
        for (; j >= 128; j >>= 1) {
            #pragma unroll
            for (int r = 0; r < 4; ++r) sk[tid * 4 + r] = key[r];
            __syncthreads();
            #pragma unroll
            for (int r = 0; r < 4; ++r) {
                int i = tid * 4 + r;
                unsigned long long pk = sk[i ^ j];
                bool up = ((i & k) == 0);
                bool lo = ((i & j) == 0);
                unsigned long long mn = key[r] < pk ? key[r] : pk;
                unsigned long long mx = key[r] < pk ? pk : key[r];
                key[r] = (lo == up) ? mn : mx;
            }
            __syncthreads();
        }
        for (; j >= 4; j >>= 1) {
            int lm = j >> 2;
            #pragma unroll
            for (int r = 0; r < 4; ++r) {
                unsigned long long pk = __shfl_xor_sync(0xffffffffu, key[r], lm);
                int i = tid * 4 + r;
                bool up = ((i & k) == 0);
                bool lo = ((i & j) == 0);
                unsigned long long mn = key[r] < pk ? key[r] : pk;
                unsigned long long mx = key[r] < pk ? pk : key[r];
                key[r] = (lo == up) ? mn : mx;
            }
        }
        if (k >= 4) {
            #pragma unroll
            for (int r = 0; r < 2; ++r) {
                int i = tid * 4 + r;
                bool up = ((i & k) == 0);
                unsigned long long a = key[r], c2 = key[r + 2];
                unsigned long long mn = a < c2 ? a : c2;
                unsigned long long mx = a < c2 ? c2 : a;
                key[r]     = up ? mn : mx;
                key[r + 2] = up ? mx : mn;
            }
        }
        #pragma unroll
        for (int p = 0; p < 2; ++p) {
            int r0 = p * 2;
            int i = tid * 4 + r0;
            bool up = ((i & k) == 0);
            unsigned long long a = key[r0], c2 = key[r0 + 1];
            unsigned long long mn = a < c2 ? a : c2;
            unsigned long long mx = a < c2 ? c2 : a;
            key[r0]     = up ? mn : mx;
            key[r0 + 1] = up ? mx : mn;
        }
    }

    const int ok = BNUM * DHID;
    const int os = ok + BNUM * KKEEP;
    #pragma unroll
    for (int r = 0; r < 4; ++r) {
        int pos = tid * 4 + r;
        unsigned long long kv = key[r];
        unsigned int enc = ~(unsigned int)(kv >> 32);
        unsigned int bits = (enc & 0x80000000u) ? (enc ^ 0x80000000u) : ~enc;
        float s = __uint_as_float(bits);
        int idx = (int)(unsigned int)(kv & 0xFFFFFFFFu);
        if (pos < KKEEP) {
            out[ok + b * KKEEP + pos] = s;
            int g = b * EPB + idx;
            smask[ei[g]         - b * NPB] = 1.f;
            smask[ei[E_TOT + g] - b * NPB] = 1.f;
        } else {
            out[os + b * KDROP + (pos - KKEEP)] = -s;
        }
    }
    __syncthreads();

    // fused segment-sum
    const int d = tid & 63, q = tid >> 6;    // q 0..15
    const size_t nb = (size_t)b * NPB;
    float s = 0.f;
    #pragma unroll 8
    for (int n = q; n < NPB; n += 16)
        s = fmaf(smask[n], hmat[(nb + n) * 64 + d], s);
    red[q][d] = s;
    __syncthreads();
    if (tid < 64) {
        float t = 0.f;
        #pragma unroll
        for (int qq = 0; qq < 16; ++qq) t += red[qq][tid];
        out[b * 64 + tid] = t;
    }
}

// ---------------------------------------------------------------------------
extern "C" void kernel_launch(void* const* d_in, const int* in_sizes, int n_in,
                              void* d_out, int out_size) {
    const float* hmat = (const float*)d_in[0];
    const float* W1   = (const float*)d_in[1];
    const float* b1   = (const float*)d_in[2];
    const float* W2   = (const float*)d_in[3];
    const float* b2   = (const float*)d_in[4];
    const int*   ei   = (const int*)  d_in[5];
    float* out = (float*)d_out;

    const int smem1 = (64 * 256 + 64 * 68) * 4;   // 82944 B -> 2 CTAs/SM
    cudaFuncSetAttribute(k1_gemm, cudaFuncAttributeMaxDynamicSharedMemorySize, smem1);

    k1_gemm<<<4096, 512, smem1>>>(hmat, W1);
    k2_edges<<<BNUM * 2, 512>>>(b1, W2, b2, ei);
    k3_sort<<<BNUM, 1024>>>(ei, hmat, out);
}

// round 9
// speedup vs baseline: 1.0469x; 1.0469x over previous
#include <cuda_runtime.h>
#include <cstdint>

#define E_TOT  (256*4096)
#define NNODE  (256*512)
#define DHID   64
#define BNUM   256
#define EPB    4096
#define NPB    512
#define KKEEP  1024
#define KDROP  3072

// chunk-major AB: [batch][chunk 0..127][node 0..511] float4
__device__ float g_AB[(size_t)BNUM * 128 * 512 * 4];
__device__ float g_scores[E_TOT];

__device__ __forceinline__ unsigned long long pk2(float x, float y) {
    unsigned long long r;
    asm("mov.b64 %0, {%1, %2};" : "=l"(r) : "f"(x), "f"(y));
    return r;
}
__device__ __forceinline__ void fma2(unsigned long long& d,
                                     unsigned long long a, unsigned long long b) {
    asm("fma.rn.f32x2 %0, %1, %2, %0;" : "+l"(d) : "l"(a), "l"(b));
}

// ---------------------------------------------------------------------------
// K1: AB = h @ Wc. CTA = 64 rows x 256 cols (half of Wc), 256 thr, 8x8 tile.
// h stored PRE-DUPLICATED in SMEM as (h,h) 8-byte pairs: inner loop has zero
// pack movs; 4 broadcast LDS.128 (h) + 2 conflict-free LDS.128 (W) per k-iter.
// ---------------------------------------------------------------------------
__global__ void __launch_bounds__(256, 2) k1_gemm(const float* __restrict__ hmat,
                                                  const float* __restrict__ W1) {
    extern __shared__ float sm1[];
    float* Ws = sm1;                                        // [64][256]  64 KB
    unsigned long long* hs2 = (unsigned long long*)(sm1 + 64 * 256); // [64][66] dup pairs
    const int tid  = threadIdx.x;
    const int tile = blockIdx.x >> 1;
    const int half = blockIdx.x & 1;          // 0 = A-half of W1, 1 = B-half
    const int rowbase = tile * 64;
    const int b     = rowbase >> 9;
    const int nboff = rowbase & 511;

    #pragma unroll
    for (int j = 0; j < 16; ++j) {
        int i = tid + j * 256;
        int k = i >> 6, o4 = i & 63;
        *(float4*)(Ws + k * 256 + o4 * 4) =
            *(const float4*)(W1 + (size_t)(half * 64 + k) * 256 + o4 * 4);
    }
    #pragma unroll
    for (int j = 0; j < 4; ++j) {
        int i = tid + j * 256;
        int n = i >> 4, k4 = i & 15;
        float4 v = *(const float4*)(hmat + (size_t)(rowbase + n) * 64 + k4 * 4);
        hs2[(k4 * 4 + 0) * 66 + n] = pk2(v.x, v.x);
        hs2[(k4 * 4 + 1) * 66 + n] = pk2(v.y, v.y);
        hs2[(k4 * 4 + 2) * 66 + n] = pk2(v.z, v.z);
        hs2[(k4 * 4 + 3) * 66 + n] = pk2(v.w, v.w);
    }
    __syncthreads();

    const int w = tid >> 5, l = tid & 31;
    const int r0 = w * 8;          // 8 rows per warp

    unsigned long long acc[8][4];  // [row][pair]: 0,1 = cols 4l..; 2,3 = 128+4l..
    #pragma unroll
    for (int i = 0; i < 8; ++i)
        #pragma unroll
        for (int p = 0; p < 4; ++p) acc[i][p] = 0ull;

    const unsigned long long* hrow = hs2 + r0;
    const float* Wcol = Ws + 4 * l;
    #pragma unroll 4
    for (int k = 0; k < 64; ++k) {
        // 4 broadcast LDS.128: duplicated (h,h) pairs for rows r0..r0+7
        ulonglong2 hd0 = *(const ulonglong2*)(hrow + k * 66);
        ulonglong2 hd1 = *(const ulonglong2*)(hrow + k * 66 + 2);
        ulonglong2 hd2 = *(const ulonglong2*)(hrow + k * 66 + 4);
        ulonglong2 hd3 = *(const ulonglong2*)(hrow + k * 66 + 6);
        ulonglong2 w0 = *(const ulonglong2*)(Wcol + k * 256);        // conflict-free
        ulonglong2 w1 = *(const ulonglong2*)(Wcol + k * 256 + 128);  // conflict-free
        unsigned long long hv[8] = {hd0.x, hd0.y, hd1.x, hd1.y,
                                    hd2.x, hd2.y, hd3.x, hd3.y};
        #pragma unroll
        for (int i = 0; i < 8; ++i) {
            fma2(acc[i][0], hv[i], w0.x); fma2(acc[i][1], hv[i], w0.y);
            fma2(acc[i][2], hv[i], w1.x); fma2(acc[i][3], hv[i], w1.y);
        }
    }

    // restage chunk-major: lane covers chunk l (cols 4l..) and chunk 32+l
    __syncthreads();
    float4* st = (float4*)sm1;    // [64][65] float4 (aliased, 66.6 KB)
    #pragma unroll
    for (int i = 0; i < 8; ++i) {
        int node = r0 + i;
        float4 v0, v1;
        *(unsigned long long*)&v0.x = acc[i][0];
        *(unsigned long long*)&v0.z = acc[i][1];
        *(unsigned long long*)&v1.x = acc[i][2];
        *(unsigned long long*)&v1.z = acc[i][3];
        st[l * 65 + node]        = v0;   // chunk l
        st[(32 + l) * 65 + node] = v1;   // chunk 32 + l
    }
    __syncthreads();
    float4* dst = (float4*)g_AB;
    #pragma unroll
    for (int j = 0; j < 16; ++j) {
        int idx = tid + j * 256;              // 0..4095
        int cc = idx >> 6, node = idx & 63;
        dst[((size_t)b * 128 + half * 64 + cc) * 512 + nboff + node] = st[cc * 65 + node];
    }
}

// ---------------------------------------------------------------------------
// K2: edge scores, 2 CTAs/batch, chunk-4 streaming, prefetch depth 2 (R7).
// ---------------------------------------------------------------------------
__global__ void __launch_bounds__(512) k2_edges(const float* __restrict__ b1,
                                                const float* __restrict__ W2,
                                                const float* __restrict__ b2p,
                                                const int*   __restrict__ ei) {
    __shared__ float As[2][512 * 4];
    __shared__ float Bs[2][512 * 4];
    __shared__ float w2s[256];
    __shared__ float b1s[256];
    const int tid = threadIdx.x;
    const int b   = blockIdx.x >> 1;
    const int eh  = blockIdx.x & 1;
    const int ebase = b * EPB + eh * 2048;

    if (tid < 64)       *(float4*)(w2s + tid * 4)        = *(const float4*)(W2 + tid * 4);
    else if (tid < 128) *(float4*)(b1s + (tid - 64) * 4) = *(const float4*)(b1 + (tid - 64) * 4);

    int roff[4], coff[4];
    float acc[4];
    #pragma unroll
    for (int i = 0; i < 4; ++i) {
        int e = ebase + tid + i * 512;
        roff[i] = (ei[e]         - b * NPB) * 4;
        coff[i] = (ei[E_TOT + e] - b * NPB) * 4;
        acc[i] = 0.f;
    }

    const float4* gA = (const float4*)g_AB + (size_t)b * 128 * 512;
    float4 ra0 = gA[tid],                     rb0 = gA[(size_t)64 * 512 + tid];
    float4 ra1 = gA[(size_t)1 * 512 + tid],   rb1 = gA[(size_t)65 * 512 + tid];
    __syncthreads();

    for (int c = 0; c < 64; ++c) {
        const int buf = c & 1;
        float4 bv = *(const float4*)(b1s + c * 4);
        float4 wa;
        wa.x = ra0.x + bv.x; wa.y = ra0.y + bv.y;
        wa.z = ra0.z + bv.z; wa.w = ra0.w + bv.w;
        *(float4*)(As[buf] + tid * 4) = wa;
        *(float4*)(Bs[buf] + tid * 4) = rb0;
        __syncthreads();
        ra0 = ra1; rb0 = rb1;
        if (c + 2 < 64) {
            ra1 = gA[(size_t)(c + 2)  * 512 + tid];
            rb1 = gA[(size_t)(c + 66) * 512 + tid];
        }
        const float4 w2v = *(const float4*)(w2s + c * 4);
        const float* Ab = As[buf];
        const float* Bb = Bs[buf];
        #pragma unroll
        for (int i = 0; i < 4; ++i) {
            float4 av = *(const float4*)(Ab + roff[i]);
            float4 b4 = *(const float4*)(Bb + coff[i]);
            float s = acc[i];
            s = fmaf(fmaxf(av.x + b4.x, 0.f), w2v.x, s);
            s = fmaf(fmaxf(av.y + b4.y, 0.f), w2v.y, s);
            s = fmaf(fmaxf(av.z + b4.z, 0.f), w2v.z, s);
            s = fmaf(fmaxf(av.w + b4.w, 0.f), w2v.w, s);
            acc[i] = s;
        }
    }
    const float b2v = b2p[0];
    #pragma unroll
    for (int i = 0; i < 4; ++i)
        g_scores[ebase + tid + i * 512] = acc[i] + b2v;
}

// ---------------------------------------------------------------------------
// K3: bitonic argsort + outputs + SMEM mask + fused segment-sum.
// ---------------------------------------------------------------------------
__global__ void __launch_bounds__(1024) k3_sort(const int* __restrict__ ei,
                                                const float* __restrict__ hmat,
                                                float* __restrict__ out) {
    __shared__ unsigned long long sk[4096];
    __shared__ float smask[512];
    __shared__ float red[16][64];
    const int b = blockIdx.x, tid = threadIdx.x;

    if (tid < 512) smask[tid] = 0.f;

    unsigned long long key[4];
    float4 sc = *(const float4*)(g_scores + b * EPB + tid * 4);
    float sv[4] = {sc.x, sc.y, sc.z, sc.w};
    #pragma unroll
    for (int r = 0; r < 4; ++r) {
        unsigned int u = __float_as_uint(sv[r]);
        unsigned int enc = (u & 0x80000000u) ? ~u : (u | 0x80000000u);
        key[r] = ((unsigned long long)(~enc) << 32) | (unsigned int)(tid * 4 + r);
    }

    for (int k = 2; k <= 4096; k <<= 1) {
        int j = k >> 1;
        for (; j >= 128; j >>= 1) {
            #pragma unroll
            for (int r = 0; r < 4; ++r) sk[tid * 4 + r] = key[r];
            __syncthreads();
            #pragma unroll
            for (int r = 0; r < 4; ++r) {
                int i = tid * 4 + r;
                unsigned long long pk = sk[i ^ j];
                bool up = ((i & k) == 0);
                bool lo = ((i & j) == 0);
                unsigned long long mn = key[r] < pk ? key[r] : pk;
                unsigned long long mx = key[r] < pk ? pk : key[r];
                key[r] = (lo == up) ? mn : mx;
            }
            __syncthreads();
        }
        for (; j >= 4; j >>= 1) {
            int lm = j >> 2;
            #pragma unroll
            for (int r = 0; r < 4; ++r) {
                unsigned long long pk = __shfl_xor_sync(0xffffffffu, key[r], lm);
                int i = tid * 4 + r;
                bool up = ((i & k) == 0);
                bool lo = ((i & j) == 0);
                unsigned long long mn = key[r] < pk ? key[r] : pk;
                unsigned long long mx = key[r] < pk ? pk : key[r];
                key[r] = (lo == up) ? mn : mx;
            }
        }
        if (k >= 4) {
            #pragma unroll
            for (int r = 0; r < 2; ++r) {
                int i = tid * 4 + r;
                bool up = ((i & k) == 0);
                unsigned long long a = key[r], c2 = key[r + 2];
                unsigned long long mn = a < c2 ? a : c2;
                unsigned long long mx = a < c2 ? c2 : a;
                key[r]     = up ? mn : mx;
                key[r + 2] = up ? mx : mn;
            }
        }
        #pragma unroll
        for (int p = 0; p < 2; ++p) {
            int r0 = p * 2;
            int i = tid * 4 + r0;
            bool up = ((i & k) == 0);
            unsigned long long a = key[r0], c2 = key[r0 + 1];
            unsigned long long mn = a < c2 ? a : c2;
            unsigned long long mx = a < c2 ? c2 : a;
            key[r0]     = up ? mn : mx;
            key[r0 + 1] = up ? mx : mn;
        }
    }

    const int ok = BNUM * DHID;
    const int os = ok + BNUM * KKEEP;
    #pragma unroll
    for (int r = 0; r < 4; ++r) {
        int pos = tid * 4 + r;
        unsigned long long kv = key[r];
        unsigned int enc = ~(unsigned int)(kv >> 32);
        unsigned int bits = (enc & 0x80000000u) ? (enc ^ 0x80000000u) : ~enc;
        float s = __uint_as_float(bits);
        int idx = (int)(unsigned int)(kv & 0xFFFFFFFFu);
        if (pos < KKEEP) {
            out[ok + b * KKEEP + pos] = s;
            int g = b * EPB + idx;
            smask[ei[g]         - b * NPB] = 1.f;
            smask[ei[E_TOT + g] - b * NPB] = 1.f;
        } else {
            out[os + b * KDROP + (pos - KKEEP)] = -s;
        }
    }
    __syncthreads();

    // fused segment-sum
    const int d = tid & 63, q = tid >> 6;    // q 0..15
    const size_t nb = (size_t)b * NPB;
    float s = 0.f;
    #pragma unroll 8
    for (int n = q; n < NPB; n += 16)
        s = fmaf(smask[n], hmat[(nb + n) * 64 + d], s);
    red[q][d] = s;
    __syncthreads();
    if (tid < 64) {
        float t = 0.f;
        #pragma unroll
        for (int qq = 0; qq < 16; ++qq) t += red[qq][tid];
        out[b * 64 + tid] = t;
    }
}

// ---------------------------------------------------------------------------
extern "C" void kernel_launch(void* const* d_in, const int* in_sizes, int n_in,
                              void* d_out, int out_size) {
    const float* hmat = (const float*)d_in[0];
    const float* W1   = (const float*)d_in[1];
    const float* b1   = (const float*)d_in[2];
    const float* W2   = (const float*)d_in[3];
    const float* b2   = (const float*)d_in[4];
    const int*   ei   = (const int*)  d_in[5];
    float* out = (float*)d_out;

    const int smem1 = 64 * 256 * 4 + 64 * 66 * 8;   // 65536 + 33792 = 99328 B
    cudaFuncSetAttribute(k1_gemm, cudaFuncAttributeMaxDynamicSharedMemorySize, smem1);

    k1_gemm<<<4096, 256, smem1>>>(hmat, W1);
    k2_edges<<<BNUM * 2, 512>>>(b1, W2, b2, ei);
    k3_sort<<<BNUM, 1024>>>(ei, hmat, out);
}

// round 10
// speedup vs baseline: 1.1960x; 1.1424x over previous
#include <cuda_runtime.h>
#include <cstdint>

#define E_TOT  (256*4096)
#define NNODE  (256*512)
#define DHID   64
#define BNUM   256
#define EPB    4096
#define NPB    512
#define KKEEP  1024
#define KDROP  3072

// chunk-major AB: [batch][chunk 0..127][node 0..511] float4
__device__ float g_AB[(size_t)BNUM * 128 * 512 * 4];
__device__ float g_scores[E_TOT];
// row-sorted edge arrays (per batch): local row, local col, original edge id
__device__ int g_srow[E_TOT];
__device__ int g_scol[E_TOT];
__device__ int g_sid[E_TOT];

__device__ __forceinline__ unsigned long long pk2(float x, float y) {
    unsigned long long r;
    asm("mov.b64 %0, {%1, %2};" : "=l"(r) : "f"(x), "f"(y));
    return r;
}
__device__ __forceinline__ void fma2(unsigned long long& d,
                                     unsigned long long a, unsigned long long b) {
    asm("fma.rn.f32x2 %0, %1, %2, %0;" : "+l"(d) : "l"(a), "l"(b));
}

// ---------------------------------------------------------------------------
// K1: AB = h @ Wc. CTA = 64 rows x 256 cols (half), 256 thr, 8 rows x 8 cols.
// (exact R7 version - empirical best)
// ---------------------------------------------------------------------------
__global__ void __launch_bounds__(256) k1_gemm(const float* __restrict__ hmat,
                                               const float* __restrict__ W1) {
    extern __shared__ float sm1[];
    float* Ws = sm1;              // [64][256]  64 KB
    float* hs = sm1 + 64 * 256;   // [64][68]   transposed h tile
    const int tid  = threadIdx.x;
    const int tile = blockIdx.x >> 1;
    const int half = blockIdx.x & 1;
    const int rowbase = tile * 64;
    const int b     = rowbase >> 9;
    const int nboff = rowbase & 511;

    #pragma unroll
    for (int j = 0; j < 16; ++j) {
        int i = tid + j * 256;
        int k = i >> 6, o4 = i & 63;
        *(float4*)(Ws + k * 256 + o4 * 4) =
            *(const float4*)(W1 + (size_t)(half * 64 + k) * 256 + o4 * 4);
    }
    #pragma unroll
    for (int j = 0; j < 4; ++j) {
        int i = tid + j * 256;
        int n = i >> 4, k4 = i & 15;
        float4 v = *(const float4*)(hmat + (size_t)(rowbase + n) * 64 + k4 * 4);
        hs[(k4 * 4 + 0) * 68 + n] = v.x;
        hs[(k4 * 4 + 1) * 68 + n] = v.y;
        hs[(k4 * 4 + 2) * 68 + n] = v.z;
        hs[(k4 * 4 + 3) * 68 + n] = v.w;
    }
    __syncthreads();

    const int w = tid >> 5, l = tid & 31;
    const int r0 = w * 8;

    unsigned long long acc[8][4];
    #pragma unroll
    for (int i = 0; i < 8; ++i)
        #pragma unroll
        for (int p = 0; p < 4; ++p) acc[i][p] = 0ull;

    #pragma unroll 4
    for (int k = 0; k < 64; ++k) {
        float4 h0 = *(const float4*)(hs + k * 68 + r0);
        float4 h1 = *(const float4*)(hs + k * 68 + r0 + 4);
        ulonglong2 w0 = *(const ulonglong2*)(Ws + k * 256 + 4 * l);
        ulonglong2 w1 = *(const ulonglong2*)(Ws + k * 256 + 128 + 4 * l);
        float hv[8] = {h0.x, h0.y, h0.z, h0.w, h1.x, h1.y, h1.z, h1.w};
        #pragma unroll
        for (int i = 0; i < 8; ++i) {
            unsigned long long a2 = pk2(hv[i], hv[i]);
            fma2(acc[i][0], a2, w0.x); fma2(acc[i][1], a2, w0.y);
            fma2(acc[i][2], a2, w1.x); fma2(acc[i][3], a2, w1.y);
        }
    }

    __syncthreads();
    float4* st = (float4*)sm1;
    #pragma unroll
    for (int i = 0; i < 8; ++i) {
        int node = r0 + i;
        float4 v0, v1;
        *(unsigned long long*)&v0.x = acc[i][0];
        *(unsigned long long*)&v0.z = acc[i][1];
        *(unsigned long long*)&v1.x = acc[i][2];
        *(unsigned long long*)&v1.z = acc[i][3];
        st[l * 65 + node]        = v0;
        st[(32 + l) * 65 + node] = v1;
    }
    __syncthreads();
    float4* dst = (float4*)g_AB;
    #pragma unroll
    for (int j = 0; j < 16; ++j) {
        int idx = tid + j * 256;
        int cc = idx >> 6, node = idx & 63;
        dst[((size_t)b * 128 + half * 64 + cc) * 512 + nboff + node] = st[cc * 65 + node];
    }
}

// ---------------------------------------------------------------------------
// K1b: per-batch counting sort of edges by src row (512 buckets).
// Emits g_srow/g_scol/g_sid in row-sorted order.
// ---------------------------------------------------------------------------
__global__ void __launch_bounds__(512) k1b_sort(const int* __restrict__ ei) {
    __shared__ int cnt[512];
    __shared__ int wsum[16];
    const int b = blockIdx.x, tid = threadIdx.x;
    cnt[tid] = 0;
    __syncthreads();

    int r8[8], c8[8];
    #pragma unroll
    for (int i = 0; i < 8; ++i) {
        int e = tid + i * 512;
        r8[i] = ei[b * EPB + e]         - b * NPB;
        c8[i] = ei[E_TOT + b * EPB + e] - b * NPB;
        atomicAdd(&cnt[r8[i]], 1);
    }
    __syncthreads();

    // exclusive block scan over 512 counts
    const int lane = tid & 31, wid = tid >> 5;
    int v = cnt[tid];
    int x = v;
    #pragma unroll
    for (int o = 1; o < 32; o <<= 1) {
        int y = __shfl_up_sync(0xffffffffu, x, o);
        if (lane >= o) x += y;
    }
    if (lane == 31) wsum[wid] = x;
    __syncthreads();
    if (tid < 16) {
        int y = wsum[tid], z = y;
        #pragma unroll
        for (int o = 1; o < 16; o <<= 1) {
            int t = __shfl_up_sync(0xffffu, z, o);
            if (tid >= o) z += t;
        }
        wsum[tid] = z - y;
    }
    __syncthreads();
    int excl = x - v + wsum[wid];
    __syncthreads();
    cnt[tid] = excl;          // running offsets
    __syncthreads();

    #pragma unroll
    for (int i = 0; i < 8; ++i) {
        int p = atomicAdd(&cnt[r8[i]], 1);
        g_srow[b * EPB + p] = r8[i];
        g_scol[b * EPB + p] = c8[i];
        g_sid [b * EPB + p] = tid + i * 512;
    }
}

// ---------------------------------------------------------------------------
// K2: edge scores on ROW-SORTED edges. 2 CTAs/batch, 4 sorted edges/thread.
// A-side gather amortized by row-reuse (sorted => ~7/8 same-row neighbors).
// ---------------------------------------------------------------------------
__global__ void __launch_bounds__(512) k2_edges(const float* __restrict__ b1,
                                                const float* __restrict__ W2,
                                                const float* __restrict__ b2p) {
    __shared__ float As[2][512 * 4];
    __shared__ float Bs[2][512 * 4];
    __shared__ float w2s[256];
    __shared__ float b1s[256];
    const int tid = threadIdx.x;
    const int b   = blockIdx.x >> 1;
    const int eh  = blockIdx.x & 1;
    const int ebase = b * EPB + eh * 2048;

    if (tid < 64)       *(float4*)(w2s + tid * 4)        = *(const float4*)(W2 + tid * 4);
    else if (tid < 128) *(float4*)(b1s + (tid - 64) * 4) = *(const float4*)(b1 + (tid - 64) * 4);

    const int4 r4 = *(const int4*)(g_srow + ebase + tid * 4);
    const int4 c4 = *(const int4*)(g_scol + ebase + tid * 4);
    const int4 id4 = *(const int4*)(g_sid + ebase + tid * 4);
    const int ro0 = r4.x * 4, ro1 = r4.y * 4, ro2 = r4.z * 4, ro3 = r4.w * 4;
    const int co0 = c4.x * 4, co1 = c4.y * 4, co2 = c4.z * 4, co3 = c4.w * 4;
    float a0 = 0.f, a1 = 0.f, a2c = 0.f, a3 = 0.f;

    const float4* gA = (const float4*)g_AB + (size_t)b * 128 * 512;
    float4 ra0 = gA[tid],                     rb0 = gA[(size_t)64 * 512 + tid];
    float4 ra1 = gA[(size_t)1 * 512 + tid],   rb1 = gA[(size_t)65 * 512 + tid];
    __syncthreads();

    for (int c = 0; c < 64; ++c) {
        const int buf = c & 1;
        float4 bv = *(const float4*)(b1s + c * 4);
        float4 wa;
        wa.x = ra0.x + bv.x; wa.y = ra0.y + bv.y;
        wa.z = ra0.z + bv.z; wa.w = ra0.w + bv.w;
        *(float4*)(As[buf] + tid * 4) = wa;
        *(float4*)(Bs[buf] + tid * 4) = rb0;
        __syncthreads();
        ra0 = ra1; rb0 = rb1;
        if (c + 2 < 64) {
            ra1 = gA[(size_t)(c + 2)  * 512 + tid];
            rb1 = gA[(size_t)(c + 66) * 512 + tid];
        }
        const float4 w2v = *(const float4*)(w2s + c * 4);
        const float* Ab = As[buf];
        const float* Bb = Bs[buf];

        float4 av = *(const float4*)(Ab + ro0);
        {
            float4 b4 = *(const float4*)(Bb + co0);
            a0 = fmaf(fmaxf(av.x + b4.x, 0.f), w2v.x, a0);
            a0 = fmaf(fmaxf(av.y + b4.y, 0.f), w2v.y, a0);
            a0 = fmaf(fmaxf(av.z + b4.z, 0.f), w2v.z, a0);
            a0 = fmaf(fmaxf(av.w + b4.w, 0.f), w2v.w, a0);
        }
        if (ro1 != ro0) av = *(const float4*)(Ab + ro1);
        {
            float4 b4 = *(const float4*)(Bb + co1);
            a1 = fmaf(fmaxf(av.x + b4.x, 0.f), w2v.x, a1);
            a1 = fmaf(fmaxf(av.y + b4.y, 0.f), w2v.y, a1);
            a1 = fmaf(fmaxf(av.z + b4.z, 0.f), w2v.z, a1);
            a1 = fmaf(fmaxf(av.w + b4.w, 0.f), w2v.w, a1);
        }
        if (ro2 != ro1) av = *(const float4*)(Ab + ro2);
        {
            float4 b4 = *(const float4*)(Bb + co2);
            a2c = fmaf(fmaxf(av.x + b4.x, 0.f), w2v.x, a2c);
            a2c = fmaf(fmaxf(av.y + b4.y, 0.f), w2v.y, a2c);
            a2c = fmaf(fmaxf(av.z + b4.z, 0.f), w2v.z, a2c);
            a2c = fmaf(fmaxf(av.w + b4.w, 0.f), w2v.w, a2c);
        }
        if (ro3 != ro2) av = *(const float4*)(Ab + ro3);
        {
            float4 b4 = *(const float4*)(Bb + co3);
            a3 = fmaf(fmaxf(av.x + b4.x, 0.f), w2v.x, a3);
            a3 = fmaf(fmaxf(av.y + b4.y, 0.f), w2v.y, a3);
            a3 = fmaf(fmaxf(av.z + b4.z, 0.f), w2v.z, a3);
            a3 = fmaf(fmaxf(av.w + b4.w, 0.f), w2v.w, a3);
        }
    }
    const float b2v = b2p[0];
    const int sb = b * EPB;
    g_scores[sb + id4.x] = a0 + b2v;
    g_scores[sb + id4.y] = a1 + b2v;
    g_scores[sb + id4.z] = a2c + b2v;
    g_scores[sb + id4.w] = a3 + b2v;
}

// ---------------------------------------------------------------------------
// K3: bitonic argsort + outputs + SMEM mask + fused segment-sum. (unchanged)
// ---------------------------------------------------------------------------
__global__ void __launch_bounds__(1024) k3_sort(const int* __restrict__ ei,
                                                const float* __restrict__ hmat,
                                                float* __restrict__ out) {
    __shared__ unsigned long long sk[4096];
    __shared__ float smask[512];
    __shared__ float red[16][64];
    const int b = blockIdx.x, tid = threadIdx.x;

    if (tid < 512) smask[tid] = 0.f;

    unsigned long long key[4];
    float4 sc = *(const float4*)(g_scores + b * EPB + tid * 4);
    float sv[4] = {sc.x, sc.y, sc.z, sc.w};
    #pragma unroll
    for (int r = 0; r < 4; ++r) {
        unsigned int u = __float_as_uint(sv[r]);
        unsigned int enc = (u & 0x80000000u) ? ~u : (u | 0x80000000u);
        key[r] = ((unsigned long long)(~enc) << 32) | (unsigned int)(tid * 4 + r);
    }

    for (int k = 2; k <= 4096; k <<= 1) {
        int j = k >> 1;
        for (; j >= 128; j >>= 1) {
            #pragma unroll
            for (int r = 0; r < 4; ++r) sk[tid * 4 + r] = key[r];
            __syncthreads();
            #pragma unroll
            for (int r = 0; r < 4; ++r) {
                int i = tid * 4 + r;
                unsigned long long pk = sk[i ^ j];
                bool up = ((i & k) == 0);
                bool lo = ((i & j) == 0);
                unsigned long long mn = key[r] < pk ? key[r] : pk;
                unsigned long long mx = key[r] < pk ? pk : key[r];
                key[r] = (lo == up) ? mn : mx;
            }
            __syncthreads();
        }
        for (; j >= 4; j >>= 1) {
            int lm = j >> 2;
            #pragma unroll
            for (int r = 0; r < 4; ++r) {
                unsigned long long pk = __shfl_xor_sync(0xffffffffu, key[r], lm);
                int i = tid * 4 + r;
                bool up = ((i & k) == 0);
                bool lo = ((i & j) == 0);
                unsigned long long mn = key[r] < pk ? key[r] : pk;
                unsigned long long mx = key[r] < pk ? pk : key[r];
                key[r] = (lo == up) ? mn : mx;
            }
        }
        if (k >= 4) {
            #pragma unroll
            for (int r = 0; r < 2; ++r) {
                int i = tid * 4 + r;
                bool up = ((i & k) == 0);
                unsigned long long a = key[r], c2 = key[r + 2];
                unsigned long long mn = a < c2 ? a : c2;
                unsigned long long mx = a < c2 ? c2 : a;
                key[r]     = up ? mn : mx;
                key[r + 2] = up ? mx : mn;
            }
        }
        #pragma unroll
        for (int p = 0; p < 2; ++p) {
            int r0 = p * 2;
            int i = tid * 4 + r0;
            bool up = ((i & k) == 0);
            unsigned long long a = key[r0], c2 = key[r0 + 1];
            unsigned long long mn = a < c2 ? a : c2;
            unsigned long long mx = a < c2 ? c2 : a;
            key[r0]     = up ? mn : mx;
            key[r0 + 1] = up ? mx : mn;
        }
    }

    const int ok = BNUM * DHID;
    const int os = ok + BNUM * KKEEP;
    #pragma unroll
    for (int r = 0; r < 4; ++r) {
        int pos = tid * 4 + r;
        unsigned long long kv = key[r];
        unsigned int enc = ~(unsigned int)(kv >> 32);
        unsigned int bits = (enc & 0x80000000u) ? (enc ^ 0x80000000u) : ~enc;
        float s = __uint_as_float(bits);
        int idx = (int)(unsigned int)(kv & 0xFFFFFFFFu);
        if (pos < KKEEP) {
            out[ok + b * KKEEP + pos] = s;
            int g = b * EPB + idx;
            smask[ei[g]         - b * NPB] = 1.f;
            smask[ei[E_TOT + g] - b * NPB] = 1.f;
        } else {
            out[os + b * KDROP + (pos - KKEEP)] = -s;
        }
    }
    __syncthreads();

    const int d = tid & 63, q = tid >> 6;
    const size_t nb = (size_t)b * NPB;
    float s = 0.f;
    #pragma unroll 8
    for (int n = q; n < NPB; n += 16)
        s = fmaf(smask[n], hmat[(nb + n) * 64 + d], s);
    red[q][d] = s;
    __syncthreads();
    if (tid < 64) {
        float t = 0.f;
        #pragma unroll
        for (int qq = 0; qq < 16; ++qq) t += red[qq][tid];
        out[b * 64 + tid] = t;
    }
}

// ---------------------------------------------------------------------------
extern "C" void kernel_launch(void* const* d_in, const int* in_sizes, int n_in,
                              void* d_out, int out_size) {
    const float* hmat = (const float*)d_in[0];
    const float* W1   = (const float*)d_in[1];
    const float* b1   = (const float*)d_in[2];
    const float* W2   = (const float*)d_in[3];
    const float* b2   = (const float*)d_in[4];
    const int*   ei   = (const int*)  d_in[5];
    float* out = (float*)d_out;

    const int smem1 = (64 * 256 + 64 * 68) * 4;   // 82944 B -> 2 CTAs/SM
    cudaFuncSetAttribute(k1_gemm, cudaFuncAttributeMaxDynamicSharedMemorySize, smem1);

    k1b_sort<<<BNUM, 512>>>(ei);
    k1_gemm<<<4096, 256, smem1>>>(hmat, W1);
    k2_edges<<<BNUM * 2, 512>>>(b1, W2, b2);
    k3_sort<<<BNUM, 1024>>>(ei, hmat, out);
}